// round 7
// baseline (speedup 1.0000x reference)
#include <cuda_runtime.h>
#include <cuda_bf16.h>
#include <cstdint>

// Problem dims (fixed by the reference)
#define H_DIM   1024
#define I_DIM   2048
#define I2_DIM  4096   // 2*I
#define N_DIM   16
#define P_DIM   33     // 2N+1
#define KCONV   4
#define BATCH   2
#define SEQ     2048
#define M_DIM   4096   // BATCH*SEQ

// Scratch (device globals: allocation-free, graph-capturable)
__device__ float g_xz[(size_t)M_DIM * I2_DIM];    // 64 MB (GEMM1 out, fp32)
__device__ float g_yz[(size_t)M_DIM * I_DIM];     // 32 MB (ssm out, tf32-rounded)
__device__ float g_xc[(size_t)M_DIM * I_DIM];     // 32 MB (conv+silu out)
__device__ float g_proj[(size_t)M_DIM * P_DIM];   // 540 KB (xproj)
__device__ float g_Aneg[I_DIM * N_DIM];
__device__ float g_xr [(size_t)M_DIM * H_DIM];    // 16 MB (x, tf32-rounded)
__device__ float g_wir[(size_t)I2_DIM * H_DIM];   // 16 MB (W_in, tf32-rounded)
__device__ float g_wor[(size_t)H_DIM * I_DIM];    //  8 MB (W_out, tf32-rounded)

__device__ __forceinline__ uint32_t rna_tf32(float f) {
    uint32_t o;
    asm("cvt.rna.tf32.f32 %0, %1;" : "=r"(o) : "f"(f));
    return o;
}
__device__ __forceinline__ uint32_t smem_u32(const void* p) {
    uint32_t a;
    asm("{ .reg .u64 t; cvta.to.shared.u64 t, %1; cvt.u32.u64 %0, t; }" : "=r"(a) : "l"(p));
    return a;
}
__device__ __forceinline__ void cp_async16(uint32_t dst, const void* src) {
    asm volatile("cp.async.cg.shared.global [%0], [%1], 16;" :: "r"(dst), "l"(src));
}

// ---------------------------------------------------------------------------
// Elementwise tf32 rounding pass
// ---------------------------------------------------------------------------
__global__ void round_tf32_kernel(const float* __restrict__ in, float* __restrict__ out,
                                  int n4) {
    int i = blockIdx.x * blockDim.x + threadIdx.x;
    if (i < n4) {
        float4 v = ((const float4*)in)[i];
        ((uint4*)out)[i] = make_uint4(rna_tf32(v.x), rna_tf32(v.y), rna_tf32(v.z), rna_tf32(v.w));
    }
}

// ===========================================================================
// TF32 GEMM via mma.sync m16n8k8, 3-stage cp.async pipeline.
// Block tile 128x128x32; 128 threads = 4 warps (2x2); warp tile 64x64.
// cp.async for chunk c+2 issued BEFORE the MMA loop (overlaps tensor work);
// fragments register-double-buffered across the 4 k-steps.
// ===========================================================================
#define BMT 128
#define BNT 128
#define BKT 32
#define PADW 36
#define BUF_FLOATS (BMT * PADW)
#define BUF_BYTES  (BUF_FLOATS * 4)
#define STAGES 3
#define GEMM_SMEM_BYTES (STAGES * 2 * BUF_BYTES)   // 110592 B

__global__ __launch_bounds__(128, 2)
void gemm_tf32_mma(const float* __restrict__ A, const float* __restrict__ B,
                   float* __restrict__ C, int M, int N, int K) {
    extern __shared__ float sm[];
    float* As = sm;
    float* Bs = sm + STAGES * BUF_FLOATS;
    const uint32_t sA = smem_u32(As);
    const uint32_t sB = smem_u32(Bs);

    const int tid  = threadIdx.x;
    const int lane = tid & 31;
    const int wid  = tid >> 5;                // 0..3
    const int wm   = wid >> 1;                // 0..1
    const int wn   = wid & 1;                 // 0..1
    const int gid  = lane >> 2;               // 0..7
    const int tig  = lane & 3;                // 0..3
    const int m0   = blockIdx.y * BMT;
    const int n0   = blockIdx.x * BNT;

    const float* Ag = A + (size_t)m0 * K;
    const float* Bg = B + (size_t)n0 * K;

    // Per-thread copy coords: 1024 float4 per operand tile, 8 per thread.
    int lm[8], lk[8];
    uint32_t soff[8];
#pragma unroll
    for (int j = 0; j < 8; j++) {
        int f = tid + 128 * j;                // 0..1023
        lm[j] = f >> 3;
        lk[j] = (f & 7) * 4;
        soff[j] = (uint32_t)(lm[j] * PADW + lk[j]) * 4u;
    }

    float acc[4][8][4];
#pragma unroll
    for (int i = 0; i < 4; i++)
#pragma unroll
        for (int j = 0; j < 8; j++)
#pragma unroll
            for (int q = 0; q < 4; q++) acc[i][j][q] = 0.f;

    const int nchunk = K / BKT;

#pragma unroll
    for (int s = 0; s < STAGES - 1; s++) {
        const int k0 = s * BKT;
        const uint32_t sa = sA + s * BUF_BYTES;
        const uint32_t sb = sB + s * BUF_BYTES;
#pragma unroll
        for (int j = 0; j < 8; j++) {
            cp_async16(sa + soff[j], Ag + (size_t)lm[j] * K + k0 + lk[j]);
            cp_async16(sb + soff[j], Bg + (size_t)lm[j] * K + k0 + lk[j]);
        }
        asm volatile("cp.async.commit_group;");
    }

    for (int c = 0; c < nchunk; c++) {
        asm volatile("cp.async.wait_group 1;");
        __syncthreads();

        // Issue copy for chunk c+2 NOW (overlaps with MMAs below).
        const int cn = c + STAGES - 1;
        if (cn < nchunk) {
            const int k0 = cn * BKT;
            const int nb = cn % STAGES;
            const uint32_t sa = sA + nb * BUF_BYTES;
            const uint32_t sb = sB + nb * BUF_BYTES;
#pragma unroll
            for (int j = 0; j < 8; j++) {
                cp_async16(sa + soff[j], Ag + (size_t)lm[j] * K + k0 + lk[j]);
                cp_async16(sb + soff[j], Bg + (size_t)lm[j] * K + k0 + lk[j]);
            }
        }
        asm volatile("cp.async.commit_group;");

        const int buf = c % STAGES;
        const uint32_t* ab = (const uint32_t*)(As + buf * BUF_FLOATS) + (wm * 64 + gid) * PADW + tig;
        const uint32_t* bb = (const uint32_t*)(Bs + buf * BUF_FLOATS) + (wn * 64 + gid) * PADW + tig;

        // Fragment double-buffer across k-steps.
        uint32_t af[2][4][4], bf[2][8][2];
#pragma unroll
        for (int i = 0; i < 4; i++) {
            af[0][i][0] = ab[(i * 16 + 0) * PADW + 0];
            af[0][i][1] = ab[(i * 16 + 8) * PADW + 0];
            af[0][i][2] = ab[(i * 16 + 0) * PADW + 4];
            af[0][i][3] = ab[(i * 16 + 8) * PADW + 4];
        }
#pragma unroll
        for (int j = 0; j < 8; j++) {
            bf[0][j][0] = bb[(j * 8) * PADW + 0];
            bf[0][j][1] = bb[(j * 8) * PADW + 4];
        }

#pragma unroll
        for (int ks = 0; ks < 4; ks++) {
            const int cur = ks & 1;
            const int nxt = cur ^ 1;
            if (ks < 3) {
                const int k1 = (ks + 1) * 8;
#pragma unroll
                for (int i = 0; i < 4; i++) {
                    af[nxt][i][0] = ab[(i * 16 + 0) * PADW + k1];
                    af[nxt][i][1] = ab[(i * 16 + 8) * PADW + k1];
                    af[nxt][i][2] = ab[(i * 16 + 0) * PADW + k1 + 4];
                    af[nxt][i][3] = ab[(i * 16 + 8) * PADW + k1 + 4];
                }
#pragma unroll
                for (int j = 0; j < 8; j++) {
                    bf[nxt][j][0] = bb[(j * 8) * PADW + k1];
                    bf[nxt][j][1] = bb[(j * 8) * PADW + k1 + 4];
                }
            }
#pragma unroll
            for (int i = 0; i < 4; i++)
#pragma unroll
                for (int j = 0; j < 8; j++) {
                    asm volatile(
                        "mma.sync.aligned.m16n8k8.row.col.f32.tf32.tf32.f32 "
                        "{%0,%1,%2,%3}, {%4,%5,%6,%7}, {%8,%9}, {%0,%1,%2,%3};"
                        : "+f"(acc[i][j][0]), "+f"(acc[i][j][1]),
                          "+f"(acc[i][j][2]), "+f"(acc[i][j][3])
                        : "r"(af[cur][i][0]), "r"(af[cur][i][1]),
                          "r"(af[cur][i][2]), "r"(af[cur][i][3]),
                          "r"(bf[cur][j][0]), "r"(bf[cur][j][1]));
                }
        }
    }

    // Epilogue
#pragma unroll
    for (int i = 0; i < 4; i++) {
        const int r0 = m0 + wm * 64 + i * 16 + gid;
#pragma unroll
        for (int j = 0; j < 8; j++) {
            const int cc = n0 + wn * 64 + j * 8 + 2 * tig;
            *(float2*)(C + (size_t)r0 * N + cc)       = make_float2(acc[i][j][0], acc[i][j][1]);
            *(float2*)(C + (size_t)(r0 + 8) * N + cc) = make_float2(acc[i][j][2], acc[i][j][3]);
        }
    }
}

// ---------------------------------------------------------------------------
// A = -exp(A_log)
// ---------------------------------------------------------------------------
__global__ void precompute_A_kernel(const float* __restrict__ A_log) {
    int idx = blockIdx.x * blockDim.x + threadIdx.x;
    if (idx < I_DIM * N_DIM) g_Aneg[idx] = -expf(A_log[idx]);
}

// ---------------------------------------------------------------------------
// Middle stage 1: depthwise conv (K=4 causal) + silu.
// ---------------------------------------------------------------------------
__global__ __launch_bounds__(256)
void conv_silu_kernel(const float* __restrict__ conv_w) {
    const int idx = blockIdx.x * blockDim.x + threadIdx.x;
    const int ig  = idx & (I_DIM / 4 - 1);
    const int mg  = idx >> 9;
    const int m0  = mg * 4;
    const int s0  = m0 & (SEQ - 1);
    const int i   = ig * 4;

    const float4 w0 = ((const float4*)conv_w)[i + 0];
    const float4 w1 = ((const float4*)conv_w)[i + 1];
    const float4 w2 = ((const float4*)conv_w)[i + 2];
    const float4 w3 = ((const float4*)conv_w)[i + 3];

    float4 r[7];
#pragma unroll
    for (int t = 0; t < 7; t++) {
        int sp = s0 - 3 + t;
        if (sp >= 0)
            r[t] = ((const float4*)g_xz)[(size_t)(m0 - 3 + t) * (I2_DIM / 4) + ig];
        else
            r[t] = make_float4(0.f, 0.f, 0.f, 0.f);
    }

#pragma unroll
    for (int o = 0; o < 4; o++) {
        float4 acc;
        acc.x = r[o].x * w0.x + r[o+1].x * w0.y + r[o+2].x * w0.z + r[o+3].x * w0.w;
        acc.y = r[o].y * w1.x + r[o+1].y * w1.y + r[o+2].y * w1.z + r[o+3].y * w1.w;
        acc.z = r[o].z * w2.x + r[o+1].z * w2.y + r[o+2].z * w2.z + r[o+3].z * w2.w;
        acc.w = r[o].w * w3.x + r[o+1].w * w3.y + r[o+2].w * w3.z + r[o+3].w * w3.w;
        acc.x = acc.x / (1.f + __expf(-acc.x));
        acc.y = acc.y / (1.f + __expf(-acc.y));
        acc.z = acc.z / (1.f + __expf(-acc.z));
        acc.w = acc.w / (1.f + __expf(-acc.w));
        ((float4*)g_xc)[(size_t)(m0 + o) * (I_DIM / 4) + ig] = acc;
    }
}

// ---------------------------------------------------------------------------
// Middle stage 2: xproj. K-chunk 512, 67.5 KB smem (2 blocks/SM).
// ---------------------------------------------------------------------------
#define PROJ_ROWS 16
#define PROJ_KC   512
#define PROJ_SMEM (P_DIM * PROJ_KC * 4)   // 67584 B

__global__ __launch_bounds__(256)
void proj_kernel(const float* __restrict__ W_x) {
    extern __shared__ float wxs[];        // [33][PROJ_KC]
    const int tid  = threadIdx.x;
    const int lane = tid & 31;
    const int wid  = tid >> 5;
    const int rb   = blockIdx.x * PROJ_ROWS;
    const int r0   = rb + wid * 2;

    const float* x0 = g_xc + (size_t)r0 * I_DIM;
    const float* x1 = g_xc + (size_t)(r0 + 1) * I_DIM;

    float acc0[P_DIM], acc1[P_DIM];
#pragma unroll
    for (int p = 0; p < P_DIM; p++) { acc0[p] = 0.f; acc1[p] = 0.f; }

    for (int k0 = 0; k0 < I_DIM; k0 += PROJ_KC) {
        __syncthreads();
        for (int f = tid; f < P_DIM * (PROJ_KC / 4); f += 256) {
            int p  = f / (PROJ_KC / 4);
            int kq = f % (PROJ_KC / 4);
            ((float4*)wxs)[p * (PROJ_KC / 4) + kq] =
                ((const float4*)(W_x + (size_t)p * I_DIM + k0))[kq];
        }
        __syncthreads();

        for (int kk = lane; kk < PROJ_KC; kk += 32) {
            float xv0 = x0[k0 + kk];
            float xv1 = x1[k0 + kk];
#pragma unroll
            for (int p = 0; p < P_DIM; p++) {
                float w = wxs[p * PROJ_KC + kk];
                acc0[p] = fmaf(xv0, w, acc0[p]);
                acc1[p] = fmaf(xv1, w, acc1[p]);
            }
        }
    }

#pragma unroll
    for (int p = 0; p < P_DIM; p++) {
        float v0 = acc0[p], v1 = acc1[p];
#pragma unroll
        for (int off = 16; off > 0; off >>= 1) {
            v0 += __shfl_down_sync(0xffffffffu, v0, off);
            v1 += __shfl_down_sync(0xffffffffu, v1, off);
        }
        if (lane == 0) {
            g_proj[(size_t)r0 * P_DIM + p]       = v0;
            g_proj[(size_t)(r0 + 1) * P_DIM + p] = v1;
        }
    }
}

// ---------------------------------------------------------------------------
// Middle stage 3: ssm + gate.
// ---------------------------------------------------------------------------
#define SSM_MT 32

__global__ __launch_bounds__(256)
void ssm_kernel(const float* __restrict__ D) {
    const int rb  = blockIdx.x * SSM_MT;
    const int tid = threadIdx.x;

    __shared__ float delta_s[SSM_MT];
    __shared__ float bc_s[SSM_MT][N_DIM];

    if (tid < SSM_MT) {
        const float* pr = g_proj + (size_t)(rb + tid) * P_DIM;
        float v = pr[0];
        delta_s[tid] = (v > 20.f) ? v : log1pf(__expf(v));
#pragma unroll
        for (int n = 0; n < N_DIM; n++)
            bc_s[tid][n] = pr[1 + n] * pr[1 + N_DIM + n];
    }
    __syncthreads();

    for (int ii = tid; ii < I_DIM; ii += 256) {
        float a[N_DIM];
        *(float4*)&a[0]  = *(const float4*)(g_Aneg + ii * N_DIM + 0);
        *(float4*)&a[4]  = *(const float4*)(g_Aneg + ii * N_DIM + 4);
        *(float4*)&a[8]  = *(const float4*)(g_Aneg + ii * N_DIM + 8);
        *(float4*)&a[12] = *(const float4*)(g_Aneg + ii * N_DIM + 12);
        const float d = D[ii];

#pragma unroll 4
        for (int mm = 0; mm < SSM_MT; mm++) {
            const int m = rb + mm;
            const float delta = delta_s[mm];
            float acc = d;
#pragma unroll
            for (int n = 0; n < N_DIM; n++)
                acc = fmaf(bc_s[mm][n], __expf(delta * a[n]), acc);
            float xcv = g_xc[(size_t)m * I_DIM + ii];
            float zv  = g_xz[(size_t)m * I2_DIM + I_DIM + ii];
            float gz  = zv / (1.f + __expf(-zv));
            g_yz[(size_t)m * I_DIM + ii] = __uint_as_float(rna_tf32(xcv * acc * gz));
        }
    }
}

// ---------------------------------------------------------------------------
// Launcher
// ---------------------------------------------------------------------------
extern "C" void kernel_launch(void* const* d_in, const int* in_sizes, int n_in,
                              void* d_out, int out_size) {
    const float* x      = (const float*)d_in[0];
    const float* W_in   = (const float*)d_in[1];
    const float* conv_w = (const float*)d_in[2];
    const float* W_x    = (const float*)d_in[3];
    const float* A_log  = (const float*)d_in[4];
    const float* D      = (const float*)d_in[5];
    const float* W_out  = (const float*)d_in[6];
    float* out = (float*)d_out;

    float *xz_ptr, *yz_ptr, *xr_ptr, *wir_ptr, *wor_ptr;
    cudaGetSymbolAddress((void**)&xz_ptr,  g_xz);
    cudaGetSymbolAddress((void**)&yz_ptr,  g_yz);
    cudaGetSymbolAddress((void**)&xr_ptr,  g_xr);
    cudaGetSymbolAddress((void**)&wir_ptr, g_wir);
    cudaGetSymbolAddress((void**)&wor_ptr, g_wor);

    cudaFuncSetAttribute(gemm_tf32_mma,
                         cudaFuncAttributeMaxDynamicSharedMemorySize, GEMM_SMEM_BYTES);
    cudaFuncSetAttribute(proj_kernel,
                         cudaFuncAttributeMaxDynamicSharedMemorySize, PROJ_SMEM);

    precompute_A_kernel<<<(I_DIM * N_DIM + 255) / 256, 256>>>(A_log);

    {
        int n4x = (M_DIM * H_DIM) / 4;
        round_tf32_kernel<<<(n4x + 255) / 256, 256>>>(x, xr_ptr, n4x);
        int n4w = (I2_DIM * H_DIM) / 4;
        round_tf32_kernel<<<(n4w + 255) / 256, 256>>>(W_in, wir_ptr, n4w);
        int n4o = (H_DIM * I_DIM) / 4;
        round_tf32_kernel<<<(n4o + 255) / 256, 256>>>(W_out, wor_ptr, n4o);
    }

    // 1) xz = x @ W_in^T
    {
        dim3 grid(I2_DIM / BNT, M_DIM / BMT);
        gemm_tf32_mma<<<grid, 128, GEMM_SMEM_BYTES>>>(xr_ptr, wir_ptr, xz_ptr,
                                                      M_DIM, I2_DIM, H_DIM);
    }

    // 2) middle
    conv_silu_kernel<<<(M_DIM / 4) * (I_DIM / 4) / 256, 256>>>(conv_w);
    proj_kernel<<<M_DIM / PROJ_ROWS, 256, PROJ_SMEM>>>(W_x);
    ssm_kernel<<<M_DIM / SSM_MT, 256>>>(D);

    // 3) out = yz @ W_out^T
    {
        dim3 grid(H_DIM / BNT, M_DIM / BMT);
        gemm_tf32_mma<<<grid, 128, GEMM_SMEM_BYTES>>>(yz_ptr, wor_ptr, out,
                                                      M_DIM, H_DIM, I_DIM);
    }
}

// round 8
// speedup vs baseline: 1.0009x; 1.0009x over previous
#include <cuda_runtime.h>
#include <cuda_bf16.h>
#include <cstdint>

// Problem dims (fixed by the reference)
#define H_DIM   1024
#define I_DIM   2048
#define I2_DIM  4096   // 2*I
#define N_DIM   16
#define P_DIM   33     // 2N+1
#define KCONV   4
#define BATCH   2
#define SEQ     2048
#define M_DIM   4096   // BATCH*SEQ

// Scratch (device globals: allocation-free, graph-capturable)
__device__ float g_xz[(size_t)M_DIM * I2_DIM];    // 64 MB (GEMM1 out, fp32)
__device__ float g_yz[(size_t)M_DIM * I_DIM];     // 32 MB (ssm out, tf32-rounded)
__device__ float g_xc[(size_t)M_DIM * I_DIM];     // 32 MB (conv+silu out)
__device__ float g_proj[(size_t)M_DIM * P_DIM];   // 540 KB (xproj)
__device__ float g_Aneg[I_DIM * N_DIM];
__device__ float g_xr [(size_t)M_DIM * H_DIM];    // 16 MB (x, tf32-rounded)
__device__ float g_wir[(size_t)I2_DIM * H_DIM];   // 16 MB (W_in, tf32-rounded)
__device__ float g_wor[(size_t)H_DIM * I_DIM];    //  8 MB (W_out, tf32-rounded)

__device__ __forceinline__ uint32_t rna_tf32(float f) {
    uint32_t o;
    asm("cvt.rna.tf32.f32 %0, %1;" : "=r"(o) : "f"(f));
    return o;
}
__device__ __forceinline__ uint32_t smem_u32(const void* p) {
    uint32_t a;
    asm("{ .reg .u64 t; cvta.to.shared.u64 t, %1; cvt.u32.u64 %0, t; }" : "=r"(a) : "l"(p));
    return a;
}
__device__ __forceinline__ void cp_async16(uint32_t dst, const void* src) {
    asm volatile("cp.async.cg.shared.global [%0], [%1], 16;" :: "r"(dst), "l"(src));
}

// ---------------------------------------------------------------------------
// Elementwise tf32 rounding pass
// ---------------------------------------------------------------------------
__global__ void round_tf32_kernel(const float* __restrict__ in, float* __restrict__ out,
                                  int n4) {
    int i = blockIdx.x * blockDim.x + threadIdx.x;
    if (i < n4) {
        float4 v = ((const float4*)in)[i];
        ((uint4*)out)[i] = make_uint4(rna_tf32(v.x), rna_tf32(v.y), rna_tf32(v.z), rna_tf32(v.w));
    }
}

// ===========================================================================
// TF32 GEMM via mma.sync m16n8k8, 3-stage cp.async pipeline.
// Templated block tile BM x BN (warp grid WMxWN, warp tile 64x64 fixed),
// 256 threads, BKT=32. R6 mainloop ordering (MMAs, then next cp.async).
// ===========================================================================
#define BKT 32
#define PADW 36

template<int BM, int BN, int WM, int WN>
__global__ __launch_bounds__(256, 1)
void gemm_tf32_big(const float* __restrict__ A, const float* __restrict__ B,
                   float* __restrict__ C, int M, int N, int K) {
    constexpr int ABUF = BM * PADW;          // floats per A stage
    constexpr int BBUF = BN * PADW;
    constexpr int NA4  = BM / 32;            // float4 copies per thread (A)
    constexpr int NB4  = BN / 32;

    extern __shared__ float sm[];
    float* As = sm;                           // [3][ABUF]
    float* Bs = sm + 3 * ABUF;                // [3][BBUF]
    const uint32_t sA = smem_u32(As);
    const uint32_t sB = smem_u32(Bs);

    const int tid  = threadIdx.x;
    const int lane = tid & 31;
    const int wid  = tid >> 5;                // 0..7
    const int wm   = wid / WN;                // 0..WM-1
    const int wn   = wid % WN;                // 0..WN-1
    const int gid  = lane >> 2;               // 0..7
    const int tig  = lane & 3;                // 0..3
    const int m0   = blockIdx.y * BM;
    const int n0   = blockIdx.x * BN;

    const float* Ag = A + (size_t)m0 * K;
    const float* Bg = B + (size_t)n0 * K;

    // Per-thread copy coords
    int lmA[NA4], lkA[NA4]; uint32_t soA[NA4];
#pragma unroll
    for (int j = 0; j < NA4; j++) {
        int f = tid + 256 * j;                // 0 .. BM*8-1
        lmA[j] = f >> 3;
        lkA[j] = (f & 7) * 4;
        soA[j] = (uint32_t)(lmA[j] * PADW + lkA[j]) * 4u;
    }
    int lmB[NB4], lkB[NB4]; uint32_t soB[NB4];
#pragma unroll
    for (int j = 0; j < NB4; j++) {
        int f = tid + 256 * j;
        lmB[j] = f >> 3;
        lkB[j] = (f & 7) * 4;
        soB[j] = (uint32_t)(lmB[j] * PADW + lkB[j]) * 4u;
    }

    float acc[4][8][4];
#pragma unroll
    for (int i = 0; i < 4; i++)
#pragma unroll
        for (int j = 0; j < 8; j++)
#pragma unroll
            for (int q = 0; q < 4; q++) acc[i][j][q] = 0.f;

    const int nchunk = K / BKT;

#pragma unroll
    for (int s = 0; s < 2; s++) {
        const int k0 = s * BKT;
        const uint32_t sa = sA + s * (ABUF * 4);
        const uint32_t sb = sB + s * (BBUF * 4);
#pragma unroll
        for (int j = 0; j < NA4; j++)
            cp_async16(sa + soA[j], Ag + (size_t)lmA[j] * K + k0 + lkA[j]);
#pragma unroll
        for (int j = 0; j < NB4; j++)
            cp_async16(sb + soB[j], Bg + (size_t)lmB[j] * K + k0 + lkB[j]);
        asm volatile("cp.async.commit_group;");
    }

    for (int c = 0; c < nchunk; c++) {
        asm volatile("cp.async.wait_group 1;");
        __syncthreads();

        const int buf = c % 3;
        const uint32_t* ab = (const uint32_t*)(As + buf * ABUF) + (wm * 64 + gid) * PADW + tig;
        const uint32_t* bb = (const uint32_t*)(Bs + buf * BBUF) + (wn * 64 + gid) * PADW + tig;
#pragma unroll
        for (int ks = 0; ks < 4; ks++) {
            const int k0 = ks * 8;
            uint32_t af[4][4];
#pragma unroll
            for (int i = 0; i < 4; i++) {
                af[i][0] = ab[(i * 16 + 0) * PADW + k0];
                af[i][1] = ab[(i * 16 + 8) * PADW + k0];
                af[i][2] = ab[(i * 16 + 0) * PADW + k0 + 4];
                af[i][3] = ab[(i * 16 + 8) * PADW + k0 + 4];
            }
            uint32_t bf[8][2];
#pragma unroll
            for (int j = 0; j < 8; j++) {
                bf[j][0] = bb[(j * 8) * PADW + k0];
                bf[j][1] = bb[(j * 8) * PADW + k0 + 4];
            }
#pragma unroll
            for (int i = 0; i < 4; i++)
#pragma unroll
                for (int j = 0; j < 8; j++) {
                    asm volatile(
                        "mma.sync.aligned.m16n8k8.row.col.f32.tf32.tf32.f32 "
                        "{%0,%1,%2,%3}, {%4,%5,%6,%7}, {%8,%9}, {%0,%1,%2,%3};"
                        : "+f"(acc[i][j][0]), "+f"(acc[i][j][1]),
                          "+f"(acc[i][j][2]), "+f"(acc[i][j][3])
                        : "r"(af[i][0]), "r"(af[i][1]), "r"(af[i][2]), "r"(af[i][3]),
                          "r"(bf[j][0]), "r"(bf[j][1]));
                }
        }

        const int cn = c + 2;
        if (cn < nchunk) {
            const int k0 = cn * BKT;
            const int nb = cn % 3;
            const uint32_t sa = sA + nb * (ABUF * 4);
            const uint32_t sb = sB + nb * (BBUF * 4);
#pragma unroll
            for (int j = 0; j < NA4; j++)
                cp_async16(sa + soA[j], Ag + (size_t)lmA[j] * K + k0 + lkA[j]);
#pragma unroll
            for (int j = 0; j < NB4; j++)
                cp_async16(sb + soB[j], Bg + (size_t)lmB[j] * K + k0 + lkB[j]);
        }
        asm volatile("cp.async.commit_group;");
    }

    // Epilogue
#pragma unroll
    for (int i = 0; i < 4; i++) {
        const int r0 = m0 + wm * 64 + i * 16 + gid;
#pragma unroll
        for (int j = 0; j < 8; j++) {
            const int cc = n0 + wn * 64 + j * 8 + 2 * tig;
            *(float2*)(C + (size_t)r0 * N + cc)       = make_float2(acc[i][j][0], acc[i][j][1]);
            *(float2*)(C + (size_t)(r0 + 8) * N + cc) = make_float2(acc[i][j][2], acc[i][j][3]);
        }
    }
}

// GEMM1: 128x256 (warps 2x4);  GEMM2: 256x128 (warps 4x2)
#define SMEM_G1 (3 * (128 + 256) * PADW * 4)   // 165888 B
#define SMEM_G2 (3 * (256 + 128) * PADW * 4)   // 165888 B

// ---------------------------------------------------------------------------
// A = -exp(A_log)
// ---------------------------------------------------------------------------
__global__ void precompute_A_kernel(const float* __restrict__ A_log) {
    int idx = blockIdx.x * blockDim.x + threadIdx.x;
    if (idx < I_DIM * N_DIM) g_Aneg[idx] = -expf(A_log[idx]);
}

// ---------------------------------------------------------------------------
// Middle stage 1: depthwise conv (K=4 causal) + silu.
// ---------------------------------------------------------------------------
__global__ __launch_bounds__(256)
void conv_silu_kernel(const float* __restrict__ conv_w) {
    const int idx = blockIdx.x * blockDim.x + threadIdx.x;
    const int ig  = idx & (I_DIM / 4 - 1);
    const int mg  = idx >> 9;
    const int m0  = mg * 4;
    const int s0  = m0 & (SEQ - 1);
    const int i   = ig * 4;

    const float4 w0 = ((const float4*)conv_w)[i + 0];
    const float4 w1 = ((const float4*)conv_w)[i + 1];
    const float4 w2 = ((const float4*)conv_w)[i + 2];
    const float4 w3 = ((const float4*)conv_w)[i + 3];

    float4 r[7];
#pragma unroll
    for (int t = 0; t < 7; t++) {
        int sp = s0 - 3 + t;
        if (sp >= 0)
            r[t] = ((const float4*)g_xz)[(size_t)(m0 - 3 + t) * (I2_DIM / 4) + ig];
        else
            r[t] = make_float4(0.f, 0.f, 0.f, 0.f);
    }

#pragma unroll
    for (int o = 0; o < 4; o++) {
        float4 acc;
        acc.x = r[o].x * w0.x + r[o+1].x * w0.y + r[o+2].x * w0.z + r[o+3].x * w0.w;
        acc.y = r[o].y * w1.x + r[o+1].y * w1.y + r[o+2].y * w1.z + r[o+3].y * w1.w;
        acc.z = r[o].z * w2.x + r[o+1].z * w2.y + r[o+2].z * w2.z + r[o+3].z * w2.w;
        acc.w = r[o].w * w3.x + r[o+1].w * w3.y + r[o+2].w * w3.z + r[o+3].w * w3.w;
        acc.x = acc.x / (1.f + __expf(-acc.x));
        acc.y = acc.y / (1.f + __expf(-acc.y));
        acc.z = acc.z / (1.f + __expf(-acc.z));
        acc.w = acc.w / (1.f + __expf(-acc.w));
        ((float4*)g_xc)[(size_t)(m0 + o) * (I_DIM / 4) + ig] = acc;
    }
}

// ---------------------------------------------------------------------------
// Middle stage 2: xproj. K-chunk 512, 67.5 KB smem (2 blocks/SM).
// ---------------------------------------------------------------------------
#define PROJ_ROWS 16
#define PROJ_KC   512
#define PROJ_SMEM (P_DIM * PROJ_KC * 4)   // 67584 B

__global__ __launch_bounds__(256)
void proj_kernel(const float* __restrict__ W_x) {
    extern __shared__ float wxs[];
    const int tid  = threadIdx.x;
    const int lane = tid & 31;
    const int wid  = tid >> 5;
    const int rb   = blockIdx.x * PROJ_ROWS;
    const int r0   = rb + wid * 2;

    const float* x0 = g_xc + (size_t)r0 * I_DIM;
    const float* x1 = g_xc + (size_t)(r0 + 1) * I_DIM;

    float acc0[P_DIM], acc1[P_DIM];
#pragma unroll
    for (int p = 0; p < P_DIM; p++) { acc0[p] = 0.f; acc1[p] = 0.f; }

    for (int k0 = 0; k0 < I_DIM; k0 += PROJ_KC) {
        __syncthreads();
        for (int f = tid; f < P_DIM * (PROJ_KC / 4); f += 256) {
            int p  = f / (PROJ_KC / 4);
            int kq = f % (PROJ_KC / 4);
            ((float4*)wxs)[p * (PROJ_KC / 4) + kq] =
                ((const float4*)(W_x + (size_t)p * I_DIM + k0))[kq];
        }
        __syncthreads();

        for (int kk = lane; kk < PROJ_KC; kk += 32) {
            float xv0 = x0[k0 + kk];
            float xv1 = x1[k0 + kk];
#pragma unroll
            for (int p = 0; p < P_DIM; p++) {
                float w = wxs[p * PROJ_KC + kk];
                acc0[p] = fmaf(xv0, w, acc0[p]);
                acc1[p] = fmaf(xv1, w, acc1[p]);
            }
        }
    }

#pragma unroll
    for (int p = 0; p < P_DIM; p++) {
        float v0 = acc0[p], v1 = acc1[p];
#pragma unroll
        for (int off = 16; off > 0; off >>= 1) {
            v0 += __shfl_down_sync(0xffffffffu, v0, off);
            v1 += __shfl_down_sync(0xffffffffu, v1, off);
        }
        if (lane == 0) {
            g_proj[(size_t)r0 * P_DIM + p]       = v0;
            g_proj[(size_t)(r0 + 1) * P_DIM + p] = v1;
        }
    }
}

// ---------------------------------------------------------------------------
// Middle stage 3: ssm + gate.
// ---------------------------------------------------------------------------
#define SSM_MT 32

__global__ __launch_bounds__(256)
void ssm_kernel(const float* __restrict__ D) {
    const int rb  = blockIdx.x * SSM_MT;
    const int tid = threadIdx.x;

    __shared__ float delta_s[SSM_MT];
    __shared__ float bc_s[SSM_MT][N_DIM];

    if (tid < SSM_MT) {
        const float* pr = g_proj + (size_t)(rb + tid) * P_DIM;
        float v = pr[0];
        delta_s[tid] = (v > 20.f) ? v : log1pf(__expf(v));
#pragma unroll
        for (int n = 0; n < N_DIM; n++)
            bc_s[tid][n] = pr[1 + n] * pr[1 + N_DIM + n];
    }
    __syncthreads();

    for (int ii = tid; ii < I_DIM; ii += 256) {
        float a[N_DIM];
        *(float4*)&a[0]  = *(const float4*)(g_Aneg + ii * N_DIM + 0);
        *(float4*)&a[4]  = *(const float4*)(g_Aneg + ii * N_DIM + 4);
        *(float4*)&a[8]  = *(const float4*)(g_Aneg + ii * N_DIM + 8);
        *(float4*)&a[12] = *(const float4*)(g_Aneg + ii * N_DIM + 12);
        const float d = D[ii];

#pragma unroll 4
        for (int mm = 0; mm < SSM_MT; mm++) {
            const int m = rb + mm;
            const float delta = delta_s[mm];
            float acc = d;
#pragma unroll
            for (int n = 0; n < N_DIM; n++)
                acc = fmaf(bc_s[mm][n], __expf(delta * a[n]), acc);
            float xcv = g_xc[(size_t)m * I_DIM + ii];
            float zv  = g_xz[(size_t)m * I2_DIM + I_DIM + ii];
            float gz  = zv / (1.f + __expf(-zv));
            g_yz[(size_t)m * I_DIM + ii] = __uint_as_float(rna_tf32(xcv * acc * gz));
        }
    }
}

// ---------------------------------------------------------------------------
// Launcher
// ---------------------------------------------------------------------------
extern "C" void kernel_launch(void* const* d_in, const int* in_sizes, int n_in,
                              void* d_out, int out_size) {
    const float* x      = (const float*)d_in[0];
    const float* W_in   = (const float*)d_in[1];
    const float* conv_w = (const float*)d_in[2];
    const float* W_x    = (const float*)d_in[3];
    const float* A_log  = (const float*)d_in[4];
    const float* D      = (const float*)d_in[5];
    const float* W_out  = (const float*)d_in[6];
    float* out = (float*)d_out;

    float *xz_ptr, *yz_ptr, *xr_ptr, *wir_ptr, *wor_ptr;
    cudaGetSymbolAddress((void**)&xz_ptr,  g_xz);
    cudaGetSymbolAddress((void**)&yz_ptr,  g_yz);
    cudaGetSymbolAddress((void**)&xr_ptr,  g_xr);
    cudaGetSymbolAddress((void**)&wir_ptr, g_wir);
    cudaGetSymbolAddress((void**)&wor_ptr, g_wor);

    cudaFuncSetAttribute((const void*)gemm_tf32_big<128, 256, 2, 4>,
                         cudaFuncAttributeMaxDynamicSharedMemorySize, SMEM_G1);
    cudaFuncSetAttribute((const void*)gemm_tf32_big<256, 128, 4, 2>,
                         cudaFuncAttributeMaxDynamicSharedMemorySize, SMEM_G2);
    cudaFuncSetAttribute(proj_kernel,
                         cudaFuncAttributeMaxDynamicSharedMemorySize, PROJ_SMEM);

    precompute_A_kernel<<<(I_DIM * N_DIM + 255) / 256, 256>>>(A_log);

    {
        int n4x = (M_DIM * H_DIM) / 4;
        round_tf32_kernel<<<(n4x + 255) / 256, 256>>>(x, xr_ptr, n4x);
        int n4w = (I2_DIM * H_DIM) / 4;
        round_tf32_kernel<<<(n4w + 255) / 256, 256>>>(W_in, wir_ptr, n4w);
        int n4o = (H_DIM * I_DIM) / 4;
        round_tf32_kernel<<<(n4o + 255) / 256, 256>>>(W_out, wor_ptr, n4o);
    }

    // 1) xz = x @ W_in^T : M=4096, N=4096, K=1024 ; tile 128x256
    {
        dim3 grid(I2_DIM / 256, M_DIM / 128);
        gemm_tf32_big<128, 256, 2, 4><<<grid, 256, SMEM_G1>>>(xr_ptr, wir_ptr, xz_ptr,
                                                              M_DIM, I2_DIM, H_DIM);
    }

    // 2) middle
    conv_silu_kernel<<<(M_DIM / 4) * (I_DIM / 4) / 256, 256>>>(conv_w);
    proj_kernel<<<M_DIM / PROJ_ROWS, 256, PROJ_SMEM>>>(W_x);
    ssm_kernel<<<M_DIM / SSM_MT, 256>>>(D);

    // 3) out = yz @ W_out^T : M=4096, N=1024, K=2048 ; tile 256x128
    {
        dim3 grid(H_DIM / 128, M_DIM / 256);
        gemm_tf32_big<256, 128, 4, 2><<<grid, 256, SMEM_G2>>>(yz_ptr, wor_ptr, out,
                                                              M_DIM, H_DIM, I_DIM);
    }
}

// round 9
// speedup vs baseline: 1.4627x; 1.4614x over previous
#include <cuda_runtime.h>
#include <cuda_fp16.h>
#include <cstdint>

// Problem dims (fixed by the reference)
#define H_DIM   1024
#define I_DIM   2048
#define I2_DIM  4096   // 2*I
#define N_DIM   16
#define P_DIM   33     // 2N+1
#define KCONV   4
#define BATCH   2
#define SEQ     2048
#define M_DIM   4096   // BATCH*SEQ

// Scratch (device globals: allocation-free, graph-capturable)
__device__ float  g_xz[(size_t)M_DIM * I2_DIM];    // 64 MB (GEMM1 out, fp32)
__device__ __half g_yzh[(size_t)M_DIM * I_DIM];    // 16 MB (ssm out, fp16)
__device__ float  g_xc[(size_t)M_DIM * I_DIM];     // 32 MB (conv+silu out)
__device__ float  g_proj[(size_t)M_DIM * P_DIM];   // 540 KB
__device__ float  g_Aneg[I_DIM * N_DIM];
__device__ __half g_xrh [(size_t)M_DIM * H_DIM];   // 8 MB (x, fp16)
__device__ __half g_wirh[(size_t)I2_DIM * H_DIM];  // 8 MB (W_in, fp16)
__device__ __half g_worh[(size_t)H_DIM * I_DIM];   // 4 MB (W_out, fp16)

__device__ __forceinline__ uint32_t smem_u32(const void* p) {
    uint32_t a;
    asm("{ .reg .u64 t; cvta.to.shared.u64 t, %1; cvt.u32.u64 %0, t; }" : "=r"(a) : "l"(p));
    return a;
}
__device__ __forceinline__ void cp_async16(uint32_t dst, const void* src) {
    asm volatile("cp.async.cg.shared.global [%0], [%1], 16;" :: "r"(dst), "l"(src));
}
__device__ __forceinline__ uint32_t h2_u32(__half2 h) {
    union { __half2 h; uint32_t u; } cv; cv.h = h; return cv.u;
}

// ---------------------------------------------------------------------------
// Elementwise fp32 -> fp16 (RN) pass: 8 floats per thread.
// ---------------------------------------------------------------------------
__global__ void round_f16_kernel(const float* __restrict__ in, __half* __restrict__ out,
                                 int n8) {
    int i = blockIdx.x * blockDim.x + threadIdx.x;
    if (i < n8) {
        float4 a = ((const float4*)in)[2 * i];
        float4 b = ((const float4*)in)[2 * i + 1];
        uint4 u;
        u.x = h2_u32(__floats2half2_rn(a.x, a.y));
        u.y = h2_u32(__floats2half2_rn(a.z, a.w));
        u.z = h2_u32(__floats2half2_rn(b.x, b.y));
        u.w = h2_u32(__floats2half2_rn(b.z, b.w));
        ((uint4*)out)[i] = u;
    }
}

// ===========================================================================
// FP16 GEMM via mma.sync m16n8k16 (fp32 accum), 3-stage cp.async pipeline.
// C[m,n] = sum_k A[m,k]*B[n,k]; A,B fp16 in gmem. Block tile 128x128x64(k);
// 128 threads = 4 warps (2x2), warp tile 64x64. Smem rows: 64 halves padded
// to 72 (36 b32) -> fragment LDS bank = (4*gid + tig) mod 32, conflict-free.
// ===========================================================================
#define BKH  64                    // k-halves per chunk (128 B/row)
#define PADH 72                    // halves per smem row
#define ABUF32 (128 * (PADH / 2))  // b32 per operand stage = 4608
#define STAGE_BYTES (ABUF32 * 4)   // 18432 B
#define GEMM_SMEM_BYTES (3 * 2 * STAGE_BYTES)   // 110592 B

__global__ __launch_bounds__(128, 2)
void gemm_f16_mma(const __half* __restrict__ A, const __half* __restrict__ B,
                  float* __restrict__ C, int M, int N, int K) {
    extern __shared__ uint32_t smw[];
    uint32_t* As = smw;                       // [3][ABUF32]
    uint32_t* Bs = smw + 3 * ABUF32;
    const uint32_t sA = smem_u32(As);
    const uint32_t sB = smem_u32(Bs);

    const int tid  = threadIdx.x;
    const int lane = tid & 31;
    const int wid  = tid >> 5;                // 0..3
    const int wm   = wid >> 1;                // 0..1
    const int wn   = wid & 1;                 // 0..1
    const int gid  = lane >> 2;               // 0..7
    const int tig  = lane & 3;                // 0..3
    const int m0   = blockIdx.y * 128;
    const int n0   = blockIdx.x * 128;

    const __half* Ag = A + (size_t)m0 * K;
    const __half* Bg = B + (size_t)n0 * K;

    // Copy coords: per operand stage = 128 rows x 128 B = 1024 x 16B; 8/thread.
    int lm[8], lk[8];
    uint32_t soff[8];
#pragma unroll
    for (int j = 0; j < 8; j++) {
        int f = tid + 128 * j;                // 0..1023
        lm[j] = f >> 3;                       // row
        lk[j] = (f & 7) * 8;                  // k offset in halves
        soff[j] = (uint32_t)(lm[j] * (PADH * 2) + (f & 7) * 16);   // bytes
    }

    float acc[4][8][4];
#pragma unroll
    for (int i = 0; i < 4; i++)
#pragma unroll
        for (int j = 0; j < 8; j++)
#pragma unroll
            for (int q = 0; q < 4; q++) acc[i][j][q] = 0.f;

    const int nchunk = K / BKH;

#pragma unroll
    for (int s = 0; s < 2; s++) {
        const int k0 = s * BKH;
        const uint32_t sa = sA + s * STAGE_BYTES;
        const uint32_t sb = sB + s * STAGE_BYTES;
#pragma unroll
        for (int j = 0; j < 8; j++) {
            cp_async16(sa + soff[j], Ag + (size_t)lm[j] * K + k0 + lk[j]);
            cp_async16(sb + soff[j], Bg + (size_t)lm[j] * K + k0 + lk[j]);
        }
        asm volatile("cp.async.commit_group;");
    }

    for (int c = 0; c < nchunk; c++) {
        asm volatile("cp.async.wait_group 1;");
        __syncthreads();

        const int buf = c % 3;
        const uint32_t* ab = As + buf * ABUF32 + (wm * 64 + gid) * (PADH / 2) + tig;
        const uint32_t* bb = Bs + buf * ABUF32 + (wn * 64 + gid) * (PADH / 2) + tig;
#pragma unroll
        for (int ks = 0; ks < 4; ks++) {       // 4 x k16 = 64 halves
            const int k0 = ks * 8;             // b32 offset
            uint32_t af[4][4];
#pragma unroll
            for (int i = 0; i < 4; i++) {
                af[i][0] = ab[(i * 16 + 0) * (PADH / 2) + k0];
                af[i][1] = ab[(i * 16 + 8) * (PADH / 2) + k0];
                af[i][2] = ab[(i * 16 + 0) * (PADH / 2) + k0 + 4];
                af[i][3] = ab[(i * 16 + 8) * (PADH / 2) + k0 + 4];
            }
            uint32_t bf[8][2];
#pragma unroll
            for (int j = 0; j < 8; j++) {
                bf[j][0] = bb[(j * 8) * (PADH / 2) + k0];
                bf[j][1] = bb[(j * 8) * (PADH / 2) + k0 + 4];
            }
#pragma unroll
            for (int i = 0; i < 4; i++)
#pragma unroll
                for (int j = 0; j < 8; j++) {
                    asm volatile(
                        "mma.sync.aligned.m16n8k16.row.col.f32.f16.f16.f32 "
                        "{%0,%1,%2,%3}, {%4,%5,%6,%7}, {%8,%9}, {%0,%1,%2,%3};"
                        : "+f"(acc[i][j][0]), "+f"(acc[i][j][1]),
                          "+f"(acc[i][j][2]), "+f"(acc[i][j][3])
                        : "r"(af[i][0]), "r"(af[i][1]), "r"(af[i][2]), "r"(af[i][3]),
                          "r"(bf[j][0]), "r"(bf[j][1]));
                }
        }

        const int cn = c + 2;
        if (cn < nchunk) {
            const int k0 = cn * BKH;
            const int nb = cn % 3;
            const uint32_t sa = sA + nb * STAGE_BYTES;
            const uint32_t sb = sB + nb * STAGE_BYTES;
#pragma unroll
            for (int j = 0; j < 8; j++) {
                cp_async16(sa + soff[j], Ag + (size_t)lm[j] * K + k0 + lk[j]);
                cp_async16(sb + soff[j], Bg + (size_t)lm[j] * K + k0 + lk[j]);
            }
        }
        asm volatile("cp.async.commit_group;");
    }

    // Epilogue (fp32 accumulators)
#pragma unroll
    for (int i = 0; i < 4; i++) {
        const int r0 = m0 + wm * 64 + i * 16 + gid;
#pragma unroll
        for (int j = 0; j < 8; j++) {
            const int cc = n0 + wn * 64 + j * 8 + 2 * tig;
            *(float2*)(C + (size_t)r0 * N + cc)       = make_float2(acc[i][j][0], acc[i][j][1]);
            *(float2*)(C + (size_t)(r0 + 8) * N + cc) = make_float2(acc[i][j][2], acc[i][j][3]);
        }
    }
}

// ---------------------------------------------------------------------------
// A = -exp(A_log)
// ---------------------------------------------------------------------------
__global__ void precompute_A_kernel(const float* __restrict__ A_log) {
    int idx = blockIdx.x * blockDim.x + threadIdx.x;
    if (idx < I_DIM * N_DIM) g_Aneg[idx] = -expf(A_log[idx]);
}

// ---------------------------------------------------------------------------
// Middle stage 1: depthwise conv (K=4 causal) + silu.
// ---------------------------------------------------------------------------
__global__ __launch_bounds__(256)
void conv_silu_kernel(const float* __restrict__ conv_w) {
    const int idx = blockIdx.x * blockDim.x + threadIdx.x;
    const int ig  = idx & (I_DIM / 4 - 1);
    const int mg  = idx >> 9;
    const int m0  = mg * 4;
    const int s0  = m0 & (SEQ - 1);
    const int i   = ig * 4;

    const float4 w0 = ((const float4*)conv_w)[i + 0];
    const float4 w1 = ((const float4*)conv_w)[i + 1];
    const float4 w2 = ((const float4*)conv_w)[i + 2];
    const float4 w3 = ((const float4*)conv_w)[i + 3];

    float4 r[7];
#pragma unroll
    for (int t = 0; t < 7; t++) {
        int sp = s0 - 3 + t;
        if (sp >= 0)
            r[t] = ((const float4*)g_xz)[(size_t)(m0 - 3 + t) * (I2_DIM / 4) + ig];
        else
            r[t] = make_float4(0.f, 0.f, 0.f, 0.f);
    }

#pragma unroll
    for (int o = 0; o < 4; o++) {
        float4 acc;
        acc.x = r[o].x * w0.x + r[o+1].x * w0.y + r[o+2].x * w0.z + r[o+3].x * w0.w;
        acc.y = r[o].y * w1.x + r[o+1].y * w1.y + r[o+2].y * w1.z + r[o+3].y * w1.w;
        acc.z = r[o].z * w2.x + r[o+1].z * w2.y + r[o+2].z * w2.z + r[o+3].z * w2.w;
        acc.w = r[o].w * w3.x + r[o+1].w * w3.y + r[o+2].w * w3.z + r[o+3].w * w3.w;
        acc.x = acc.x / (1.f + __expf(-acc.x));
        acc.y = acc.y / (1.f + __expf(-acc.y));
        acc.z = acc.z / (1.f + __expf(-acc.z));
        acc.w = acc.w / (1.f + __expf(-acc.w));
        ((float4*)g_xc)[(size_t)(m0 + o) * (I_DIM / 4) + ig] = acc;
    }
}

// ---------------------------------------------------------------------------
// Middle stage 2: xproj. K-chunk 512, 67.5 KB smem (2 blocks/SM).
// ---------------------------------------------------------------------------
#define PROJ_ROWS 16
#define PROJ_KC   512
#define PROJ_SMEM (P_DIM * PROJ_KC * 4)   // 67584 B

__global__ __launch_bounds__(256)
void proj_kernel(const float* __restrict__ W_x) {
    extern __shared__ float wxs[];
    const int tid  = threadIdx.x;
    const int lane = tid & 31;
    const int wid  = tid >> 5;
    const int rb   = blockIdx.x * PROJ_ROWS;
    const int r0   = rb + wid * 2;

    const float* x0 = g_xc + (size_t)r0 * I_DIM;
    const float* x1 = g_xc + (size_t)(r0 + 1) * I_DIM;

    float acc0[P_DIM], acc1[P_DIM];
#pragma unroll
    for (int p = 0; p < P_DIM; p++) { acc0[p] = 0.f; acc1[p] = 0.f; }

    for (int k0 = 0; k0 < I_DIM; k0 += PROJ_KC) {
        __syncthreads();
        for (int f = tid; f < P_DIM * (PROJ_KC / 4); f += 256) {
            int p  = f / (PROJ_KC / 4);
            int kq = f % (PROJ_KC / 4);
            ((float4*)wxs)[p * (PROJ_KC / 4) + kq] =
                ((const float4*)(W_x + (size_t)p * I_DIM + k0))[kq];
        }
        __syncthreads();

        for (int kk = lane; kk < PROJ_KC; kk += 32) {
            float xv0 = x0[k0 + kk];
            float xv1 = x1[k0 + kk];
#pragma unroll
            for (int p = 0; p < P_DIM; p++) {
                float w = wxs[p * PROJ_KC + kk];
                acc0[p] = fmaf(xv0, w, acc0[p]);
                acc1[p] = fmaf(xv1, w, acc1[p]);
            }
        }
    }

#pragma unroll
    for (int p = 0; p < P_DIM; p++) {
        float v0 = acc0[p], v1 = acc1[p];
#pragma unroll
        for (int off = 16; off > 0; off >>= 1) {
            v0 += __shfl_down_sync(0xffffffffu, v0, off);
            v1 += __shfl_down_sync(0xffffffffu, v1, off);
        }
        if (lane == 0) {
            g_proj[(size_t)r0 * P_DIM + p]       = v0;
            g_proj[(size_t)(r0 + 1) * P_DIM + p] = v1;
        }
    }
}

// ---------------------------------------------------------------------------
// Middle stage 3: ssm + gate. Writes fp16 yz (GEMM2 A operand).
// ---------------------------------------------------------------------------
#define SSM_MT 32

__global__ __launch_bounds__(256)
void ssm_kernel(const float* __restrict__ D) {
    const int rb  = blockIdx.x * SSM_MT;
    const int tid = threadIdx.x;

    __shared__ float delta_s[SSM_MT];
    __shared__ float bc_s[SSM_MT][N_DIM];

    if (tid < SSM_MT) {
        const float* pr = g_proj + (size_t)(rb + tid) * P_DIM;
        float v = pr[0];
        delta_s[tid] = (v > 20.f) ? v : log1pf(__expf(v));
#pragma unroll
        for (int n = 0; n < N_DIM; n++)
            bc_s[tid][n] = pr[1 + n] * pr[1 + N_DIM + n];
    }
    __syncthreads();

    for (int ii = tid; ii < I_DIM; ii += 256) {
        float a[N_DIM];
        *(float4*)&a[0]  = *(const float4*)(g_Aneg + ii * N_DIM + 0);
        *(float4*)&a[4]  = *(const float4*)(g_Aneg + ii * N_DIM + 4);
        *(float4*)&a[8]  = *(const float4*)(g_Aneg + ii * N_DIM + 8);
        *(float4*)&a[12] = *(const float4*)(g_Aneg + ii * N_DIM + 12);
        const float d = D[ii];

#pragma unroll 4
        for (int mm = 0; mm < SSM_MT; mm++) {
            const int m = rb + mm;
            const float delta = delta_s[mm];
            float acc = d;
#pragma unroll
            for (int n = 0; n < N_DIM; n++)
                acc = fmaf(bc_s[mm][n], __expf(delta * a[n]), acc);
            float xcv = g_xc[(size_t)m * I_DIM + ii];
            float zv  = g_xz[(size_t)m * I2_DIM + I_DIM + ii];
            float gz  = zv / (1.f + __expf(-zv));
            g_yzh[(size_t)m * I_DIM + ii] = __float2half_rn(xcv * acc * gz);
        }
    }
}

// ---------------------------------------------------------------------------
// Launcher
// ---------------------------------------------------------------------------
extern "C" void kernel_launch(void* const* d_in, const int* in_sizes, int n_in,
                              void* d_out, int out_size) {
    const float* x      = (const float*)d_in[0];
    const float* W_in   = (const float*)d_in[1];
    const float* conv_w = (const float*)d_in[2];
    const float* W_x    = (const float*)d_in[3];
    const float* A_log  = (const float*)d_in[4];
    const float* D      = (const float*)d_in[5];
    const float* W_out  = (const float*)d_in[6];
    float* out = (float*)d_out;

    float *xz_ptr;
    __half *yzh_ptr, *xrh_ptr, *wirh_ptr, *worh_ptr;
    cudaGetSymbolAddress((void**)&xz_ptr,   g_xz);
    cudaGetSymbolAddress((void**)&yzh_ptr,  g_yzh);
    cudaGetSymbolAddress((void**)&xrh_ptr,  g_xrh);
    cudaGetSymbolAddress((void**)&wirh_ptr, g_wirh);
    cudaGetSymbolAddress((void**)&worh_ptr, g_worh);

    cudaFuncSetAttribute(gemm_f16_mma,
                         cudaFuncAttributeMaxDynamicSharedMemorySize, GEMM_SMEM_BYTES);
    cudaFuncSetAttribute(proj_kernel,
                         cudaFuncAttributeMaxDynamicSharedMemorySize, PROJ_SMEM);

    precompute_A_kernel<<<(I_DIM * N_DIM + 255) / 256, 256>>>(A_log);

    // fp32 -> fp16 operand conversion
    {
        int n8x = (M_DIM * H_DIM) / 8;
        round_f16_kernel<<<(n8x + 255) / 256, 256>>>(x, xrh_ptr, n8x);
        int n8w = (I2_DIM * H_DIM) / 8;
        round_f16_kernel<<<(n8w + 255) / 256, 256>>>(W_in, wirh_ptr, n8w);
        int n8o = (H_DIM * I_DIM) / 8;
        round_f16_kernel<<<(n8o + 255) / 256, 256>>>(W_out, worh_ptr, n8o);
    }

    // 1) xz = x @ W_in^T : M=4096, N=4096, K=1024
    {
        dim3 grid(I2_DIM / 128, M_DIM / 128);
        gemm_f16_mma<<<grid, 128, GEMM_SMEM_BYTES>>>(xrh_ptr, wirh_ptr, xz_ptr,
                                                     M_DIM, I2_DIM, H_DIM);
    }

    // 2) middle
    conv_silu_kernel<<<(M_DIM / 4) * (I_DIM / 4) / 256, 256>>>(conv_w);
    proj_kernel<<<M_DIM / PROJ_ROWS, 256, PROJ_SMEM>>>(W_x);
    ssm_kernel<<<M_DIM / SSM_MT, 256>>>(D);

    // 3) out = yz @ W_out^T : M=4096, N=1024, K=2048
    {
        dim3 grid(H_DIM / 128, M_DIM / 128);
        gemm_f16_mma<<<grid, 128, GEMM_SMEM_BYTES>>>(yzh_ptr, worh_ptr, out,
                                                     M_DIM, H_DIM, I_DIM);
    }
}

// round 10
// speedup vs baseline: 1.4745x; 1.0080x over previous
#include <cuda_runtime.h>
#include <cuda_fp16.h>
#include <cstdint>

// Problem dims (fixed by the reference)
#define H_DIM   1024
#define I_DIM   2048
#define I2_DIM  4096   // 2*I
#define N_DIM   16
#define P_DIM   33     // 2N+1
#define KCONV   4
#define BATCH   2
#define SEQ     2048
#define M_DIM   4096   // BATCH*SEQ

// Scratch (device globals: allocation-free, graph-capturable)
__device__ float  g_xz[(size_t)M_DIM * I2_DIM];    // 64 MB (GEMM1 out, fp32)
__device__ __half g_yzh[(size_t)M_DIM * I_DIM];    // 16 MB (ssm out, fp16)
__device__ float  g_xc[(size_t)M_DIM * I_DIM];     // 32 MB (conv+silu out)
__device__ float  g_proj[(size_t)M_DIM * P_DIM];   // 540 KB
__device__ float  g_Aneg[I_DIM * N_DIM];
__device__ __half g_xrh [(size_t)M_DIM * H_DIM];   // 8 MB (x, fp16)
__device__ __half g_wirh[(size_t)I2_DIM * H_DIM];  // 8 MB (W_in, fp16)
__device__ __half g_worh[(size_t)H_DIM * I_DIM];   // 4 MB (W_out, fp16)

__device__ __forceinline__ uint32_t smem_u32(const void* p) {
    uint32_t a;
    asm("{ .reg .u64 t; cvta.to.shared.u64 t, %1; cvt.u32.u64 %0, t; }" : "=r"(a) : "l"(p));
    return a;
}
__device__ __forceinline__ void cp_async16(uint32_t dst, const void* src) {
    asm volatile("cp.async.cg.shared.global [%0], [%1], 16;" :: "r"(dst), "l"(src));
}
__device__ __forceinline__ uint32_t h2_u32(__half2 h) {
    union { __half2 h; uint32_t u; } cv; cv.h = h; return cv.u;
}
#define LDSM_X4(r0, r1, r2, r3, addr) \
    asm volatile("ldmatrix.sync.aligned.m8n8.x4.shared.b16 {%0,%1,%2,%3}, [%4];" \
                 : "=r"(r0), "=r"(r1), "=r"(r2), "=r"(r3) : "r"(addr))

// ---------------------------------------------------------------------------
// Elementwise fp32 -> fp16 (RN) pass: 8 floats per thread.
// ---------------------------------------------------------------------------
__global__ void round_f16_kernel(const float* __restrict__ in, __half* __restrict__ out,
                                 int n8) {
    int i = blockIdx.x * blockDim.x + threadIdx.x;
    if (i < n8) {
        float4 a = ((const float4*)in)[2 * i];
        float4 b = ((const float4*)in)[2 * i + 1];
        uint4 u;
        u.x = h2_u32(__floats2half2_rn(a.x, a.y));
        u.y = h2_u32(__floats2half2_rn(a.z, a.w));
        u.z = h2_u32(__floats2half2_rn(b.x, b.y));
        u.w = h2_u32(__floats2half2_rn(b.z, b.w));
        ((uint4*)out)[i] = u;
    }
}

// ===========================================================================
// FP16 GEMM via mma.sync m16n8k16 (fp32 accum), 3-stage cp.async pipeline,
// ldmatrix.x4 fragment loads. Block tile 128x128x64(k); 128 threads = 4 warps
// (2x2), warp tile 64x64. Smem rows: 64 halves padded to 72 (144 B, 16B-
// aligned rows; ldmatrix phase banks 4r mod 32 -> conflict-free).
// ===========================================================================
#define BKH  64                    // k-halves per chunk (128 B/row)
#define PADH 72                    // halves per smem row
#define ROWB (PADH * 2)            // 144 bytes per row
#define ABUF32 (128 * (PADH / 2))  // b32 per operand stage = 4608
#define STAGE_BYTES (ABUF32 * 4)   // 18432 B
#define GEMM_SMEM_BYTES (3 * 2 * STAGE_BYTES)   // 110592 B

__global__ __launch_bounds__(128, 2)
void gemm_f16_mma(const __half* __restrict__ A, const __half* __restrict__ B,
                  float* __restrict__ C, int M, int N, int K) {
    extern __shared__ uint32_t smw[];
    uint32_t* As = smw;                       // [3][ABUF32]
    uint32_t* Bs = smw + 3 * ABUF32;
    const uint32_t sA = smem_u32(As);
    const uint32_t sB = smem_u32(Bs);

    const int tid  = threadIdx.x;
    const int lane = tid & 31;
    const int wid  = tid >> 5;                // 0..3
    const int wm   = wid >> 1;                // 0..1
    const int wn   = wid & 1;                 // 0..1
    const int gid  = lane >> 2;               // 0..7
    const int tig  = lane & 3;                // 0..3
    const int m0   = blockIdx.y * 128;
    const int n0   = blockIdx.x * 128;

    const __half* Ag = A + (size_t)m0 * K;
    const __half* Bg = B + (size_t)n0 * K;

    // Copy coords: per operand stage = 128 rows x 128 B = 1024 x 16B; 8/thread.
    int lm[8], lk[8];
    uint32_t soff[8];
#pragma unroll
    for (int j = 0; j < 8; j++) {
        int f = tid + 128 * j;                // 0..1023
        lm[j] = f >> 3;                       // row
        lk[j] = (f & 7) * 8;                  // k offset in halves
        soff[j] = (uint32_t)(lm[j] * ROWB + (f & 7) * 16);   // bytes
    }

    // ldmatrix lane-address components (within a stage):
    // A tile (i,ks): lane l -> row wm*64 + i*16 + (l&15), byte kb + (l>>4)*16
    const uint32_t aLane = (uint32_t)((wm * 64 + (lane & 15)) * ROWB + (lane >> 4) * 16);
    // B tile pair (jp,ks): lane l -> row wn*64 + jp*16 + (l&7) + ((l>>4)<<3),
    //                      byte kb + ((l>>3)&1)*16
    const uint32_t bLane = (uint32_t)((wn * 64 + (lane & 7) + ((lane >> 4) << 3)) * ROWB
                                      + ((lane >> 3) & 1) * 16);

    float acc[4][8][4];
#pragma unroll
    for (int i = 0; i < 4; i++)
#pragma unroll
        for (int j = 0; j < 8; j++)
#pragma unroll
            for (int q = 0; q < 4; q++) acc[i][j][q] = 0.f;

    const int nchunk = K / BKH;

#pragma unroll
    for (int s = 0; s < 2; s++) {
        const int k0 = s * BKH;
        const uint32_t sa = sA + s * STAGE_BYTES;
        const uint32_t sb = sB + s * STAGE_BYTES;
#pragma unroll
        for (int j = 0; j < 8; j++) {
            cp_async16(sa + soff[j], Ag + (size_t)lm[j] * K + k0 + lk[j]);
            cp_async16(sb + soff[j], Bg + (size_t)lm[j] * K + k0 + lk[j]);
        }
        asm volatile("cp.async.commit_group;");
    }

    for (int c = 0; c < nchunk; c++) {
        asm volatile("cp.async.wait_group 1;");
        __syncthreads();

        const int buf = c % 3;
        const uint32_t aBase = sA + buf * STAGE_BYTES + aLane;
        const uint32_t bBase = sB + buf * STAGE_BYTES + bLane;

#pragma unroll
        for (int ks = 0; ks < 4; ks++) {       // 4 x k16 = 64 halves
            const uint32_t kb = ks * 32;       // 16 halves = 32 bytes
            uint32_t af[4][4];
#pragma unroll
            for (int i = 0; i < 4; i++)
                LDSM_X4(af[i][0], af[i][1], af[i][2], af[i][3],
                        aBase + i * 16 * ROWB + kb);
            uint32_t bf[8][2];
#pragma unroll
            for (int jp = 0; jp < 4; jp++)
                LDSM_X4(bf[2 * jp][0], bf[2 * jp][1], bf[2 * jp + 1][0], bf[2 * jp + 1][1],
                        bBase + jp * 16 * ROWB + kb);
#pragma unroll
            for (int i = 0; i < 4; i++)
#pragma unroll
                for (int j = 0; j < 8; j++) {
                    asm volatile(
                        "mma.sync.aligned.m16n8k16.row.col.f32.f16.f16.f32 "
                        "{%0,%1,%2,%3}, {%4,%5,%6,%7}, {%8,%9}, {%0,%1,%2,%3};"
                        : "+f"(acc[i][j][0]), "+f"(acc[i][j][1]),
                          "+f"(acc[i][j][2]), "+f"(acc[i][j][3])
                        : "r"(af[i][0]), "r"(af[i][1]), "r"(af[i][2]), "r"(af[i][3]),
                          "r"(bf[j][0]), "r"(bf[j][1]));
                }
        }

        const int cn = c + 2;
        if (cn < nchunk) {
            const int k0 = cn * BKH;
            const int nb = cn % 3;
            const uint32_t sa = sA + nb * STAGE_BYTES;
            const uint32_t sb = sB + nb * STAGE_BYTES;
#pragma unroll
            for (int j = 0; j < 8; j++) {
                cp_async16(sa + soff[j], Ag + (size_t)lm[j] * K + k0 + lk[j]);
                cp_async16(sb + soff[j], Bg + (size_t)lm[j] * K + k0 + lk[j]);
            }
        }
        asm volatile("cp.async.commit_group;");
    }

    // Epilogue (fp32 accumulators)
#pragma unroll
    for (int i = 0; i < 4; i++) {
        const int r0 = m0 + wm * 64 + i * 16 + gid;
#pragma unroll
        for (int j = 0; j < 8; j++) {
            const int cc = n0 + wn * 64 + j * 8 + 2 * tig;
            *(float2*)(C + (size_t)r0 * N + cc)       = make_float2(acc[i][j][0], acc[i][j][1]);
            *(float2*)(C + (size_t)(r0 + 8) * N + cc) = make_float2(acc[i][j][2], acc[i][j][3]);
        }
    }
}

// ---------------------------------------------------------------------------
// A = -exp(A_log)
// ---------------------------------------------------------------------------
__global__ void precompute_A_kernel(const float* __restrict__ A_log) {
    int idx = blockIdx.x * blockDim.x + threadIdx.x;
    if (idx < I_DIM * N_DIM) g_Aneg[idx] = -expf(A_log[idx]);
}

// ---------------------------------------------------------------------------
// Middle stage 1: depthwise conv (K=4 causal) + silu.
// ---------------------------------------------------------------------------
__global__ __launch_bounds__(256)
void conv_silu_kernel(const float* __restrict__ conv_w) {
    const int idx = blockIdx.x * blockDim.x + threadIdx.x;
    const int ig  = idx & (I_DIM / 4 - 1);
    const int mg  = idx >> 9;
    const int m0  = mg * 4;
    const int s0  = m0 & (SEQ - 1);
    const int i   = ig * 4;

    const float4 w0 = ((const float4*)conv_w)[i + 0];
    const float4 w1 = ((const float4*)conv_w)[i + 1];
    const float4 w2 = ((const float4*)conv_w)[i + 2];
    const float4 w3 = ((const float4*)conv_w)[i + 3];

    float4 r[7];
#pragma unroll
    for (int t = 0; t < 7; t++) {
        int sp = s0 - 3 + t;
        if (sp >= 0)
            r[t] = ((const float4*)g_xz)[(size_t)(m0 - 3 + t) * (I2_DIM / 4) + ig];
        else
            r[t] = make_float4(0.f, 0.f, 0.f, 0.f);
    }

#pragma unroll
    for (int o = 0; o < 4; o++) {
        float4 acc;
        acc.x = r[o].x * w0.x + r[o+1].x * w0.y + r[o+2].x * w0.z + r[o+3].x * w0.w;
        acc.y = r[o].y * w1.x + r[o+1].y * w1.y + r[o+2].y * w1.z + r[o+3].y * w1.w;
        acc.z = r[o].z * w2.x + r[o+1].z * w2.y + r[o+2].z * w2.z + r[o+3].z * w2.w;
        acc.w = r[o].w * w3.x + r[o+1].w * w3.y + r[o+2].w * w3.z + r[o+3].w * w3.w;
        acc.x = acc.x / (1.f + __expf(-acc.x));
        acc.y = acc.y / (1.f + __expf(-acc.y));
        acc.z = acc.z / (1.f + __expf(-acc.z));
        acc.w = acc.w / (1.f + __expf(-acc.w));
        ((float4*)g_xc)[(size_t)(m0 + o) * (I_DIM / 4) + ig] = acc;
    }
}

// ---------------------------------------------------------------------------
// Middle stage 2: xproj. K-chunk 512, 67.5 KB smem (2 blocks/SM).
// ---------------------------------------------------------------------------
#define PROJ_ROWS 16
#define PROJ_KC   512
#define PROJ_SMEM (P_DIM * PROJ_KC * 4)   // 67584 B

__global__ __launch_bounds__(256)
void proj_kernel(const float* __restrict__ W_x) {
    extern __shared__ float wxs[];
    const int tid  = threadIdx.x;
    const int lane = tid & 31;
    const int wid  = tid >> 5;
    const int rb   = blockIdx.x * PROJ_ROWS;
    const int r0   = rb + wid * 2;

    const float* x0 = g_xc + (size_t)r0 * I_DIM;
    const float* x1 = g_xc + (size_t)(r0 + 1) * I_DIM;

    float acc0[P_DIM], acc1[P_DIM];
#pragma unroll
    for (int p = 0; p < P_DIM; p++) { acc0[p] = 0.f; acc1[p] = 0.f; }

    for (int k0 = 0; k0 < I_DIM; k0 += PROJ_KC) {
        __syncthreads();
        for (int f = tid; f < P_DIM * (PROJ_KC / 4); f += 256) {
            int p  = f / (PROJ_KC / 4);
            int kq = f % (PROJ_KC / 4);
            ((float4*)wxs)[p * (PROJ_KC / 4) + kq] =
                ((const float4*)(W_x + (size_t)p * I_DIM + k0))[kq];
        }
        __syncthreads();

        for (int kk = lane; kk < PROJ_KC; kk += 32) {
            float xv0 = x0[k0 + kk];
            float xv1 = x1[k0 + kk];
#pragma unroll
            for (int p = 0; p < P_DIM; p++) {
                float w = wxs[p * PROJ_KC + kk];
                acc0[p] = fmaf(xv0, w, acc0[p]);
                acc1[p] = fmaf(xv1, w, acc1[p]);
            }
        }
    }

#pragma unroll
    for (int p = 0; p < P_DIM; p++) {
        float v0 = acc0[p], v1 = acc1[p];
#pragma unroll
        for (int off = 16; off > 0; off >>= 1) {
            v0 += __shfl_down_sync(0xffffffffu, v0, off);
            v1 += __shfl_down_sync(0xffffffffu, v1, off);
        }
        if (lane == 0) {
            g_proj[(size_t)r0 * P_DIM + p]       = v0;
            g_proj[(size_t)(r0 + 1) * P_DIM + p] = v1;
        }
    }
}

// ---------------------------------------------------------------------------
// Middle stage 3: ssm + gate. Writes fp16 yz (GEMM2 A operand).
// ---------------------------------------------------------------------------
#define SSM_MT 32

__global__ __launch_bounds__(256)
void ssm_kernel(const float* __restrict__ D) {
    const int rb  = blockIdx.x * SSM_MT;
    const int tid = threadIdx.x;

    __shared__ float delta_s[SSM_MT];
    __shared__ float bc_s[SSM_MT][N_DIM];

    if (tid < SSM_MT) {
        const float* pr = g_proj + (size_t)(rb + tid) * P_DIM;
        float v = pr[0];
        delta_s[tid] = (v > 20.f) ? v : log1pf(__expf(v));
#pragma unroll
        for (int n = 0; n < N_DIM; n++)
            bc_s[tid][n] = pr[1 + n] * pr[1 + N_DIM + n];
    }
    __syncthreads();

    for (int ii = tid; ii < I_DIM; ii += 256) {
        float a[N_DIM];
        *(float4*)&a[0]  = *(const float4*)(g_Aneg + ii * N_DIM + 0);
        *(float4*)&a[4]  = *(const float4*)(g_Aneg + ii * N_DIM + 4);
        *(float4*)&a[8]  = *(const float4*)(g_Aneg + ii * N_DIM + 8);
        *(float4*)&a[12] = *(const float4*)(g_Aneg + ii * N_DIM + 12);
        const float d = D[ii];

#pragma unroll 4
        for (int mm = 0; mm < SSM_MT; mm++) {
            const int m = rb + mm;
            const float delta = delta_s[mm];
            float acc = d;
#pragma unroll
            for (int n = 0; n < N_DIM; n++)
                acc = fmaf(bc_s[mm][n], __expf(delta * a[n]), acc);
            float xcv = g_xc[(size_t)m * I_DIM + ii];
            float zv  = g_xz[(size_t)m * I2_DIM + I_DIM + ii];
            float gz  = zv / (1.f + __expf(-zv));
            g_yzh[(size_t)m * I_DIM + ii] = __float2half_rn(xcv * acc * gz);
        }
    }
}

// ---------------------------------------------------------------------------
// Launcher
// ---------------------------------------------------------------------------
extern "C" void kernel_launch(void* const* d_in, const int* in_sizes, int n_in,
                              void* d_out, int out_size) {
    const float* x      = (const float*)d_in[0];
    const float* W_in   = (const float*)d_in[1];
    const float* conv_w = (const float*)d_in[2];
    const float* W_x    = (const float*)d_in[3];
    const float* A_log  = (const float*)d_in[4];
    const float* D      = (const float*)d_in[5];
    const float* W_out  = (const float*)d_in[6];
    float* out = (float*)d_out;

    float *xz_ptr;
    __half *yzh_ptr, *xrh_ptr, *wirh_ptr, *worh_ptr;
    cudaGetSymbolAddress((void**)&xz_ptr,   g_xz);
    cudaGetSymbolAddress((void**)&yzh_ptr,  g_yzh);
    cudaGetSymbolAddress((void**)&xrh_ptr,  g_xrh);
    cudaGetSymbolAddress((void**)&wirh_ptr, g_wirh);
    cudaGetSymbolAddress((void**)&worh_ptr, g_worh);

    cudaFuncSetAttribute(gemm_f16_mma,
                         cudaFuncAttributeMaxDynamicSharedMemorySize, GEMM_SMEM_BYTES);
    cudaFuncSetAttribute(proj_kernel,
                         cudaFuncAttributeMaxDynamicSharedMemorySize, PROJ_SMEM);

    precompute_A_kernel<<<(I_DIM * N_DIM + 255) / 256, 256>>>(A_log);

    // fp32 -> fp16 operand conversion
    {
        int n8x = (M_DIM * H_DIM) / 8;
        round_f16_kernel<<<(n8x + 255) / 256, 256>>>(x, xrh_ptr, n8x);
        int n8w = (I2_DIM * H_DIM) / 8;
        round_f16_kernel<<<(n8w + 255) / 256, 256>>>(W_in, wirh_ptr, n8w);
        int n8o = (H_DIM * I_DIM) / 8;
        round_f16_kernel<<<(n8o + 255) / 256, 256>>>(W_out, worh_ptr, n8o);
    }

    // 1) xz = x @ W_in^T : M=4096, N=4096, K=1024
    {
        dim3 grid(I2_DIM / 128, M_DIM / 128);
        gemm_f16_mma<<<grid, 128, GEMM_SMEM_BYTES>>>(xrh_ptr, wirh_ptr, xz_ptr,
                                                     M_DIM, I2_DIM, H_DIM);
    }

    // 2) middle
    conv_silu_kernel<<<(M_DIM / 4) * (I_DIM / 4) / 256, 256>>>(conv_w);
    proj_kernel<<<M_DIM / PROJ_ROWS, 256, PROJ_SMEM>>>(W_x);
    ssm_kernel<<<M_DIM / SSM_MT, 256>>>(D);

    // 3) out = yz @ W_out^T : M=4096, N=1024, K=2048
    {
        dim3 grid(H_DIM / 128, M_DIM / 128);
        gemm_f16_mma<<<grid, 128, GEMM_SMEM_BYTES>>>(yzh_ptr, worh_ptr, out,
                                                     M_DIM, H_DIM, I_DIM);
    }
}

// round 11
// speedup vs baseline: 1.5895x; 1.0780x over previous
#include <cuda_runtime.h>
#include <cuda_fp16.h>
#include <cstdint>

// Problem dims (fixed by the reference)
#define H_DIM   1024
#define I_DIM   2048
#define I2_DIM  4096   // 2*I
#define N_DIM   16
#define P_DIM   33     // 2N+1
#define KCONV   4
#define BATCH   2
#define SEQ     2048
#define M_DIM   4096   // BATCH*SEQ

// Scratch (device globals: allocation-free, graph-capturable)
__device__ __half g_xzh[(size_t)M_DIM * I2_DIM];   // 32 MB (GEMM1 out, fp16)
__device__ __half g_yzh[(size_t)M_DIM * I_DIM];    // 16 MB (ssm out, fp16)
__device__ float  g_xc[(size_t)M_DIM * I_DIM];     // 32 MB (conv+silu out, fp32)
__device__ float  g_proj[(size_t)M_DIM * P_DIM];   // 540 KB
__device__ float  g_Aneg[I_DIM * N_DIM];
__device__ __half g_xrh [(size_t)M_DIM * H_DIM];   // 8 MB (x, fp16)
__device__ __half g_wirh[(size_t)I2_DIM * H_DIM];  // 8 MB (W_in, fp16)
__device__ __half g_worh[(size_t)H_DIM * I_DIM];   // 4 MB (W_out, fp16)

__device__ __forceinline__ uint32_t smem_u32(const void* p) {
    uint32_t a;
    asm("{ .reg .u64 t; cvta.to.shared.u64 t, %1; cvt.u32.u64 %0, t; }" : "=r"(a) : "l"(p));
    return a;
}
__device__ __forceinline__ void cp_async16(uint32_t dst, const void* src) {
    asm volatile("cp.async.cg.shared.global [%0], [%1], 16;" :: "r"(dst), "l"(src));
}
__device__ __forceinline__ uint32_t h2_u32(__half2 h) {
    union { __half2 h; uint32_t u; } cv; cv.h = h; return cv.u;
}
#define LDSM_X4(r0, r1, r2, r3, addr) \
    asm volatile("ldmatrix.sync.aligned.m8n8.x4.shared.b16 {%0,%1,%2,%3}, [%4];" \
                 : "=r"(r0), "=r"(r1), "=r"(r2), "=r"(r3) : "r"(addr))

// ---------------------------------------------------------------------------
// Fused prep: fp32->fp16 for x / W_in / W_out (8 floats per thread) and
// A = -exp(A_log) (8 floats per thread). One launch.
// ---------------------------------------------------------------------------
#define N8_X   ((M_DIM  * H_DIM) / 8)   // 524288
#define N8_WI  ((I2_DIM * H_DIM) / 8)   // 524288
#define N8_WO  ((H_DIM  * I_DIM) / 8)   // 262144
#define N8_AL  ((I_DIM  * N_DIM) / 8)   // 4096
#define N8_TOT (N8_X + N8_WI + N8_WO + N8_AL)

__device__ __forceinline__ void cvt8_f16(const float* in, __half* out, int i) {
    float4 a = ((const float4*)in)[2 * i];
    float4 b = ((const float4*)in)[2 * i + 1];
    uint4 u;
    u.x = h2_u32(__floats2half2_rn(a.x, a.y));
    u.y = h2_u32(__floats2half2_rn(a.z, a.w));
    u.z = h2_u32(__floats2half2_rn(b.x, b.y));
    u.w = h2_u32(__floats2half2_rn(b.z, b.w));
    ((uint4*)out)[i] = u;
}

__global__ void prep_kernel(const float* __restrict__ x, const float* __restrict__ W_in,
                            const float* __restrict__ W_out, const float* __restrict__ A_log) {
    int i = blockIdx.x * blockDim.x + threadIdx.x;
    if (i < N8_X) {
        cvt8_f16(x, g_xrh, i);
    } else if (i < N8_X + N8_WI) {
        cvt8_f16(W_in, g_wirh, i - N8_X);
    } else if (i < N8_X + N8_WI + N8_WO) {
        cvt8_f16(W_out, g_worh, i - N8_X - N8_WI);
    } else if (i < N8_TOT) {
        int j = i - (N8_X + N8_WI + N8_WO);
        float4 a = ((const float4*)A_log)[2 * j];
        float4 b = ((const float4*)A_log)[2 * j + 1];
        ((float4*)g_Aneg)[2 * j]     = make_float4(-expf(a.x), -expf(a.y), -expf(a.z), -expf(a.w));
        ((float4*)g_Aneg)[2 * j + 1] = make_float4(-expf(b.x), -expf(b.y), -expf(b.z), -expf(b.w));
    }
}

// ===========================================================================
// FP16 GEMM via mma.sync m16n8k16 (fp32 accum), 3-stage cp.async pipeline,
// ldmatrix.x4 fragment loads. Block tile 128x128x64(k); 128 threads = 4 warps
// (2x2), warp tile 64x64. Templated output type (float or __half).
// ===========================================================================
#define BKH  64
#define PADH 72
#define ROWB (PADH * 2)            // 144 bytes per row
#define ABUF32 (128 * (PADH / 2))  // 4608 b32 per operand stage
#define STAGE_BYTES (ABUF32 * 4)   // 18432 B
#define GEMM_SMEM_BYTES (3 * 2 * STAGE_BYTES)   // 110592 B

template<typename OutT>
__global__ __launch_bounds__(128, 2)
void gemm_f16_mma(const __half* __restrict__ A, const __half* __restrict__ B,
                  OutT* __restrict__ C, int M, int N, int K) {
    extern __shared__ uint32_t smw[];
    uint32_t* As = smw;
    uint32_t* Bs = smw + 3 * ABUF32;
    const uint32_t sA = smem_u32(As);
    const uint32_t sB = smem_u32(Bs);

    const int tid  = threadIdx.x;
    const int lane = tid & 31;
    const int wid  = tid >> 5;
    const int wm   = wid >> 1;
    const int wn   = wid & 1;
    const int gid  = lane >> 2;
    const int tig  = lane & 3;
    const int m0   = blockIdx.y * 128;
    const int n0   = blockIdx.x * 128;

    const __half* Ag = A + (size_t)m0 * K;
    const __half* Bg = B + (size_t)n0 * K;

    int lm[8], lk[8];
    uint32_t soff[8];
#pragma unroll
    for (int j = 0; j < 8; j++) {
        int f = tid + 128 * j;
        lm[j] = f >> 3;
        lk[j] = (f & 7) * 8;
        soff[j] = (uint32_t)(lm[j] * ROWB + (f & 7) * 16);
    }

    const uint32_t aLane = (uint32_t)((wm * 64 + (lane & 15)) * ROWB + (lane >> 4) * 16);
    const uint32_t bLane = (uint32_t)((wn * 64 + (lane & 7) + ((lane >> 4) << 3)) * ROWB
                                      + ((lane >> 3) & 1) * 16);

    float acc[4][8][4];
#pragma unroll
    for (int i = 0; i < 4; i++)
#pragma unroll
        for (int j = 0; j < 8; j++)
#pragma unroll
            for (int q = 0; q < 4; q++) acc[i][j][q] = 0.f;

    const int nchunk = K / BKH;

#pragma unroll
    for (int s = 0; s < 2; s++) {
        const int k0 = s * BKH;
        const uint32_t sa = sA + s * STAGE_BYTES;
        const uint32_t sb = sB + s * STAGE_BYTES;
#pragma unroll
        for (int j = 0; j < 8; j++) {
            cp_async16(sa + soff[j], Ag + (size_t)lm[j] * K + k0 + lk[j]);
            cp_async16(sb + soff[j], Bg + (size_t)lm[j] * K + k0 + lk[j]);
        }
        asm volatile("cp.async.commit_group;");
    }

    for (int c = 0; c < nchunk; c++) {
        asm volatile("cp.async.wait_group 1;");
        __syncthreads();

        const int buf = c % 3;
        const uint32_t aBase = sA + buf * STAGE_BYTES + aLane;
        const uint32_t bBase = sB + buf * STAGE_BYTES + bLane;

#pragma unroll
        for (int ks = 0; ks < 4; ks++) {
            const uint32_t kb = ks * 32;
            uint32_t af[4][4];
#pragma unroll
            for (int i = 0; i < 4; i++)
                LDSM_X4(af[i][0], af[i][1], af[i][2], af[i][3],
                        aBase + i * 16 * ROWB + kb);
            uint32_t bf[8][2];
#pragma unroll
            for (int jp = 0; jp < 4; jp++)
                LDSM_X4(bf[2 * jp][0], bf[2 * jp][1], bf[2 * jp + 1][0], bf[2 * jp + 1][1],
                        bBase + jp * 16 * ROWB + kb);
#pragma unroll
            for (int i = 0; i < 4; i++)
#pragma unroll
                for (int j = 0; j < 8; j++) {
                    asm volatile(
                        "mma.sync.aligned.m16n8k16.row.col.f32.f16.f16.f32 "
                        "{%0,%1,%2,%3}, {%4,%5,%6,%7}, {%8,%9}, {%0,%1,%2,%3};"
                        : "+f"(acc[i][j][0]), "+f"(acc[i][j][1]),
                          "+f"(acc[i][j][2]), "+f"(acc[i][j][3])
                        : "r"(af[i][0]), "r"(af[i][1]), "r"(af[i][2]), "r"(af[i][3]),
                          "r"(bf[j][0]), "r"(bf[j][1]));
                }
        }

        const int cn = c + 2;
        if (cn < nchunk) {
            const int k0 = cn * BKH;
            const int nb = cn % 3;
            const uint32_t sa = sA + nb * STAGE_BYTES;
            const uint32_t sb = sB + nb * STAGE_BYTES;
#pragma unroll
            for (int j = 0; j < 8; j++) {
                cp_async16(sa + soff[j], Ag + (size_t)lm[j] * K + k0 + lk[j]);
                cp_async16(sb + soff[j], Bg + (size_t)lm[j] * K + k0 + lk[j]);
            }
        }
        asm volatile("cp.async.commit_group;");
    }

    // Epilogue
#pragma unroll
    for (int i = 0; i < 4; i++) {
        const int r0 = m0 + wm * 64 + i * 16 + gid;
#pragma unroll
        for (int j = 0; j < 8; j++) {
            const int cc = n0 + wn * 64 + j * 8 + 2 * tig;
            if constexpr (sizeof(OutT) == 4) {
                *(float2*)((float*)C + (size_t)r0 * N + cc) =
                    make_float2(acc[i][j][0], acc[i][j][1]);
                *(float2*)((float*)C + (size_t)(r0 + 8) * N + cc) =
                    make_float2(acc[i][j][2], acc[i][j][3]);
            } else {
                *(__half2*)((__half*)C + (size_t)r0 * N + cc) =
                    __floats2half2_rn(acc[i][j][0], acc[i][j][1]);
                *(__half2*)((__half*)C + (size_t)(r0 + 8) * N + cc) =
                    __floats2half2_rn(acc[i][j][2], acc[i][j][3]);
            }
        }
    }
}

// ---------------------------------------------------------------------------
// Middle stage 1: depthwise conv (K=4 causal) + silu. Reads fp16 xz.
// ---------------------------------------------------------------------------
__device__ __forceinline__ float4 ld4h(const __half* p) {
    uint2 v = *(const uint2*)p;
    __half2 h0 = *(__half2*)&v.x;
    __half2 h1 = *(__half2*)&v.y;
    float2 f0 = __half22float2(h0);
    float2 f1 = __half22float2(h1);
    return make_float4(f0.x, f0.y, f1.x, f1.y);
}

__global__ __launch_bounds__(256)
void conv_silu_kernel(const float* __restrict__ conv_w) {
    const int idx = blockIdx.x * blockDim.x + threadIdx.x;
    const int ig  = idx & (I_DIM / 4 - 1);
    const int mg  = idx >> 9;
    const int m0  = mg * 4;
    const int s0  = m0 & (SEQ - 1);
    const int i   = ig * 4;

    const float4 w0 = ((const float4*)conv_w)[i + 0];
    const float4 w1 = ((const float4*)conv_w)[i + 1];
    const float4 w2 = ((const float4*)conv_w)[i + 2];
    const float4 w3 = ((const float4*)conv_w)[i + 3];

    float4 r[7];
#pragma unroll
    for (int t = 0; t < 7; t++) {
        int sp = s0 - 3 + t;
        if (sp >= 0)
            r[t] = ld4h(g_xzh + (size_t)(m0 - 3 + t) * I2_DIM + i);
        else
            r[t] = make_float4(0.f, 0.f, 0.f, 0.f);
    }

#pragma unroll
    for (int o = 0; o < 4; o++) {
        float4 acc;
        acc.x = r[o].x * w0.x + r[o+1].x * w0.y + r[o+2].x * w0.z + r[o+3].x * w0.w;
        acc.y = r[o].y * w1.x + r[o+1].y * w1.y + r[o+2].y * w1.z + r[o+3].y * w1.w;
        acc.z = r[o].z * w2.x + r[o+1].z * w2.y + r[o+2].z * w2.z + r[o+3].z * w2.w;
        acc.w = r[o].w * w3.x + r[o+1].w * w3.y + r[o+2].w * w3.z + r[o+3].w * w3.w;
        acc.x = acc.x / (1.f + __expf(-acc.x));
        acc.y = acc.y / (1.f + __expf(-acc.y));
        acc.z = acc.z / (1.f + __expf(-acc.z));
        acc.w = acc.w / (1.f + __expf(-acc.w));
        ((float4*)g_xc)[(size_t)(m0 + o) * (I_DIM / 4) + ig] = acc;
    }
}

// ---------------------------------------------------------------------------
// Middle stage 2: xproj. 32 rows/block (4 rows/warp); W_x chunked in smem.
// ---------------------------------------------------------------------------
#define PROJ_ROWS 32
#define PROJ_KC   512
#define PROJ_SMEM (P_DIM * PROJ_KC * 4)   // 67584 B

__global__ __launch_bounds__(256)
void proj_kernel(const float* __restrict__ W_x) {
    extern __shared__ float wxs[];
    const int tid  = threadIdx.x;
    const int lane = tid & 31;
    const int wid  = tid >> 5;
    const int r0   = blockIdx.x * PROJ_ROWS + wid * 4;

    const float* xp0 = g_xc + (size_t)(r0 + 0) * I_DIM;
    const float* xp1 = g_xc + (size_t)(r0 + 1) * I_DIM;
    const float* xp2 = g_xc + (size_t)(r0 + 2) * I_DIM;
    const float* xp3 = g_xc + (size_t)(r0 + 3) * I_DIM;

    float acc0[P_DIM], acc1[P_DIM], acc2[P_DIM], acc3[P_DIM];
#pragma unroll
    for (int p = 0; p < P_DIM; p++) { acc0[p] = 0.f; acc1[p] = 0.f; acc2[p] = 0.f; acc3[p] = 0.f; }

    for (int k0 = 0; k0 < I_DIM; k0 += PROJ_KC) {
        __syncthreads();
        for (int f = tid; f < P_DIM * (PROJ_KC / 4); f += 256) {
            int p  = f / (PROJ_KC / 4);
            int kq = f % (PROJ_KC / 4);
            ((float4*)wxs)[p * (PROJ_KC / 4) + kq] =
                ((const float4*)(W_x + (size_t)p * I_DIM + k0))[kq];
        }
        __syncthreads();

        for (int kk = lane; kk < PROJ_KC; kk += 32) {
            float x0 = xp0[k0 + kk];
            float x1 = xp1[k0 + kk];
            float x2 = xp2[k0 + kk];
            float x3 = xp3[k0 + kk];
#pragma unroll
            for (int p = 0; p < P_DIM; p++) {
                float w = wxs[p * PROJ_KC + kk];
                acc0[p] = fmaf(x0, w, acc0[p]);
                acc1[p] = fmaf(x1, w, acc1[p]);
                acc2[p] = fmaf(x2, w, acc2[p]);
                acc3[p] = fmaf(x3, w, acc3[p]);
            }
        }
    }

#pragma unroll
    for (int p = 0; p < P_DIM; p++) {
        float v0 = acc0[p], v1 = acc1[p], v2 = acc2[p], v3 = acc3[p];
#pragma unroll
        for (int off = 16; off > 0; off >>= 1) {
            v0 += __shfl_down_sync(0xffffffffu, v0, off);
            v1 += __shfl_down_sync(0xffffffffu, v1, off);
            v2 += __shfl_down_sync(0xffffffffu, v2, off);
            v3 += __shfl_down_sync(0xffffffffu, v3, off);
        }
        if (lane == 0) {
            g_proj[(size_t)(r0 + 0) * P_DIM + p] = v0;
            g_proj[(size_t)(r0 + 1) * P_DIM + p] = v1;
            g_proj[(size_t)(r0 + 2) * P_DIM + p] = v2;
            g_proj[(size_t)(r0 + 3) * P_DIM + p] = v3;
        }
    }
}

// ---------------------------------------------------------------------------
// Middle stage 3: ssm + gate. 148 blocks, 27/28 rows each (balanced fill).
// ---------------------------------------------------------------------------
#define SSM_MAXR 28

__global__ __launch_bounds__(256)
void ssm_kernel(const float* __restrict__ D) {
    const int bid  = blockIdx.x;
    const int rows = 27 + (bid < 100 ? 1 : 0);
    const int rb   = bid * 27 + (bid < 100 ? bid : 100);
    const int tid  = threadIdx.x;

    __shared__ float delta_s[SSM_MAXR];
    __shared__ float bc_s[SSM_MAXR][N_DIM];

    if (tid < rows) {
        const float* pr = g_proj + (size_t)(rb + tid) * P_DIM;
        float v = pr[0];
        delta_s[tid] = (v > 20.f) ? v : log1pf(__expf(v));
#pragma unroll
        for (int n = 0; n < N_DIM; n++)
            bc_s[tid][n] = pr[1 + n] * pr[1 + N_DIM + n];
    }
    __syncthreads();

    for (int ii = tid; ii < I_DIM; ii += 256) {
        float a[N_DIM];
        *(float4*)&a[0]  = *(const float4*)(g_Aneg + ii * N_DIM + 0);
        *(float4*)&a[4]  = *(const float4*)(g_Aneg + ii * N_DIM + 4);
        *(float4*)&a[8]  = *(const float4*)(g_Aneg + ii * N_DIM + 8);
        *(float4*)&a[12] = *(const float4*)(g_Aneg + ii * N_DIM + 12);
        const float d = D[ii];

#pragma unroll 4
        for (int mm = 0; mm < rows; mm++) {
            const int m = rb + mm;
            const float delta = delta_s[mm];
            float acc = d;
#pragma unroll
            for (int n = 0; n < N_DIM; n++)
                acc = fmaf(bc_s[mm][n], __expf(delta * a[n]), acc);
            float xcv = g_xc[(size_t)m * I_DIM + ii];
            float zv  = __half2float(g_xzh[(size_t)m * I2_DIM + I_DIM + ii]);
            float gz  = zv / (1.f + __expf(-zv));
            g_yzh[(size_t)m * I_DIM + ii] = __float2half_rn(xcv * acc * gz);
        }
    }
}

// ---------------------------------------------------------------------------
// Launcher
// ---------------------------------------------------------------------------
extern "C" void kernel_launch(void* const* d_in, const int* in_sizes, int n_in,
                              void* d_out, int out_size) {
    const float* x      = (const float*)d_in[0];
    const float* W_in   = (const float*)d_in[1];
    const float* conv_w = (const float*)d_in[2];
    const float* W_x    = (const float*)d_in[3];
    const float* A_log  = (const float*)d_in[4];
    const float* D      = (const float*)d_in[5];
    const float* W_out  = (const float*)d_in[6];
    float* out = (float*)d_out;

    __half *xzh_ptr, *yzh_ptr, *xrh_ptr, *wirh_ptr, *worh_ptr;
    cudaGetSymbolAddress((void**)&xzh_ptr,  g_xzh);
    cudaGetSymbolAddress((void**)&yzh_ptr,  g_yzh);
    cudaGetSymbolAddress((void**)&xrh_ptr,  g_xrh);
    cudaGetSymbolAddress((void**)&wirh_ptr, g_wirh);
    cudaGetSymbolAddress((void**)&worh_ptr, g_worh);

    cudaFuncSetAttribute(gemm_f16_mma<__half>,
                         cudaFuncAttributeMaxDynamicSharedMemorySize, GEMM_SMEM_BYTES);
    cudaFuncSetAttribute(gemm_f16_mma<float>,
                         cudaFuncAttributeMaxDynamicSharedMemorySize, GEMM_SMEM_BYTES);
    cudaFuncSetAttribute(proj_kernel,
                         cudaFuncAttributeMaxDynamicSharedMemorySize, PROJ_SMEM);

    // 0) fused prep: fp16 conversions + A = -exp(A_log)
    prep_kernel<<<(N8_TOT + 255) / 256, 256>>>(x, W_in, W_out, A_log);

    // 1) xz = x @ W_in^T : M=4096, N=4096, K=1024 (fp16 out)
    {
        dim3 grid(I2_DIM / 128, M_DIM / 128);
        gemm_f16_mma<__half><<<grid, 128, GEMM_SMEM_BYTES>>>(xrh_ptr, wirh_ptr, xzh_ptr,
                                                             M_DIM, I2_DIM, H_DIM);
    }

    // 2) middle
    conv_silu_kernel<<<(M_DIM / 4) * (I_DIM / 4) / 256, 256>>>(conv_w);
    proj_kernel<<<M_DIM / PROJ_ROWS, 256, PROJ_SMEM>>>(W_x);
    ssm_kernel<<<148, 256>>>(D);

    // 3) out = yz @ W_out^T : M=4096, N=1024, K=2048 (fp32 out)
    {
        dim3 grid(H_DIM / 128, M_DIM / 128);
        gemm_f16_mma<float><<<grid, 128, GEMM_SMEM_BYTES>>>(yzh_ptr, worh_ptr, out,
                                                            M_DIM, H_DIM, I_DIM);
    }
}